// round 15
// baseline (speedup 1.0000x reference)
#include <cuda_runtime.h>
#include <cuda_pipeline.h>
#include <cstdint>

// ---------------------------------------------------------------------------
// QuantumLayer: out[r] = <psi_r| U† Z5 U |psi_r>, psi_r = x_r / ||x_r||.
// Lightcone of Z5 touches only qubits {3,4,5} (top 3 index bits), so
// M = O (8x8 Hermitian) ⊗ I_8 and
//   out = ( Σ_{a,b} ReO[a][b] * dot(x[8a..], x[8b..]) ) / ||x||^2.
//
// R14 + software L2 prefetch. Every fill path is bound by a ~64-line per-SM
// fill queue: BW/SM = 8KB / latency. prefetch.global.L2 has no destination,
// bypasses that queue, and converts demand misses (DRAM ~550cyc) into L2
// hits (~240cyc) -> up to ~2.2x per-SM bandwidth within the same window.
// ---------------------------------------------------------------------------

struct c2 { float x, y; };
__device__ __forceinline__ c2 cmul(c2 a, c2 b) { return { a.x*b.x - a.y*b.y, a.x*b.y + a.y*b.x }; }
__device__ __forceinline__ c2 cadd(c2 a, c2 b) { return { a.x + b.x, a.y + b.y }; }

struct U2 { c2 m00, m01, m10, m11; };

// qiskit U(theta, phi, lam)
__device__ __forceinline__ U2 u3(float th, float ph, float la) {
    float s, c;   sincosf(0.5f * th, &s, &c);
    float sph, cph; sincosf(ph, &sph, &cph);
    float sla, cla; sincosf(la, &sla, &cla);
    float spl, cpl; sincosf(ph + la, &spl, &cpl);
    U2 u;
    u.m00 = {  c,        0.f     };
    u.m01 = { -cla * s, -sla * s };
    u.m10 = {  cph * s,  sph * s };
    u.m11 = {  cpl * c,  spl * c };
    return u;
}

template <int BIT>
__device__ __forceinline__ void apply1(c2 (&w)[8], U2 u) {
#pragma unroll
    for (int a = 0; a < 8; a++) {
        if (!(a & BIT)) {
            c2 t0 = w[a], t1 = w[a | BIT];
            w[a]       = cadd(cmul(u.m00, t0), cmul(u.m01, t1));
            w[a | BIT] = cadd(cmul(u.m10, t0), cmul(u.m11, t1));
        }
    }
}

static constexpr int WARPS   = 8;     // per block
static constexpr int TPB     = WARPS * 32;
static constexpr int WROWS   = 16;    // rows per warp-tile (2 lanes per row)
static constexpr int ROW_PAD = 72;    // 64+8 floats: conflict-free for both
                                      // STS.128 and strided LDS.128
static constexpr int WTILE   = WROWS * ROW_PAD;              // floats/stage
static constexpr int SMEM_BYTES = WARPS * 2 * WTILE * 4;     // 73728
static constexpr int PF_DIST = 4;     // prefetch distance in warp-strides

__global__ void __launch_bounds__(TPB, 3) quadform_kernel(
    const float* __restrict__ feat, const float* __restrict__ p,
    float* __restrict__ out, int n, int ntiles, int full_tiles) {
    extern __shared__ float smem[];            // [WARPS][2][WTILE]
    __shared__ float C[64];
    __shared__ float Wr[8][8];
    __shared__ float Wi[8][8];

    int tid  = threadIdx.x;
    int wid  = tid >> 5;
    int lane = tid & 31;
    float* wtile = smem + wid * (2 * WTILE);

    int gwarp  = blockIdx.x * WARPS + wid;
    int nwarps = gridDim.x * WARPS;

    // L2 evict_last policy (kept: measured best-equal variant, R8)
    uint64_t pol;
    asm("createpolicy.fractional.L2::evict_last.b64 %0, 1.0;" : "=l"(pol));

    // L2 prefetch of tile tt: 4KB = 32 lanes x 128B, one instr per lane.
    // Full tiles only (no OOB addresses).
    auto l2_prefetch = [&](int tt) {
        if (tt < full_tiles) {
            const char* a = (const char*)feat + ((size_t)tt * WROWS) * 256 + lane * 128;
            asm volatile("prefetch.global.L2 [%0];" :: "l"(a));
        }
    };

    // warp-private prefetch of 16-row tile tt into stage buf (cp.async.cg)
    auto prefetch = [&](int tt, int buf) {
        int base = tt * WROWS;
        const float4* src = reinterpret_cast<const float4*>(feat) + (size_t)base * 16;
        float* dstf = wtile + buf * WTILE;
        if (tt < full_tiles) {               // common case: no bounds checks
#pragma unroll
            for (int i = 0; i < 8; i++) {
                int v = lane + 32 * i;
                int r = v >> 4, c4 = v & 15;
                uint32_t d = (uint32_t)__cvta_generic_to_shared(&dstf[r * ROW_PAD + c4 * 4]);
                asm volatile(
                    "cp.async.cg.shared.global.L2::cache_hint [%0], [%1], 16, %2;"
                    :: "r"(d), "l"(src + v), "l"(pol) : "memory");
            }
        } else {
            int nvec = (n - base) * 16;
            for (int v = lane; v < nvec; v += 32) {
                int r = v >> 4, c4 = v & 15;
                uint32_t d = (uint32_t)__cvta_generic_to_shared(&dstf[r * ROW_PAD + c4 * 4]);
                asm volatile(
                    "cp.async.cg.shared.global.L2::cache_hint [%0], [%1], 16, %2;"
                    :: "r"(d), "l"(src + v), "l"(pol) : "memory");
            }
        }
    };

    // ---- warm L2 for the first PF_DIST tiles, then start the pipe ----
#pragma unroll
    for (int k = 1; k <= PF_DIST; k++) l2_prefetch(gwarp + k * nwarps);
    if (gwarp < ntiles) prefetch(gwarp, 0);
    __pipeline_commit();

    // ---- build ReO while first tiles stream (once per block) ----
    // 3-qubit index a: bit0=q3, bit1=q4, bit2=q5. Sub-circuit (forward):
    // U3(q3;9), U3(q4;12), U3(q5;15), CX(4->3), P(19;q3), U3(q3;26),
    // U3(q5;29), CU(35;3->5). O = W† diag(z) W, z_a = +1 iff (a&4)==0.
    if (tid < 8) {
        c2 w[8];
#pragma unroll
        for (int a = 0; a < 8; a++) w[a] = { (a == tid) ? 1.f : 0.f, 0.f };

        apply1<1>(w, u3(p[9],  p[10], p[11]));
        apply1<2>(w, u3(p[12], p[13], p[14]));
        apply1<4>(w, u3(p[15], p[16], p[17]));

        // CX control q4 (bit1) -> target q3 (bit0)
#pragma unroll
        for (int a = 0; a < 8; a++)
            if ((a & 2) && !(a & 1)) { c2 tmp = w[a]; w[a] = w[a | 1]; w[a | 1] = tmp; }

        // P(params[19]) on q3 (bit0)
        {
            float sp, cp; sincosf(p[19], &sp, &cp);
            c2 e = { cp, sp };
#pragma unroll
            for (int a = 0; a < 8; a++) if (a & 1) w[a] = cmul(w[a], e);
        }

        apply1<1>(w, u3(p[26], p[27], p[28]));
        apply1<4>(w, u3(p[29], p[30], p[31]));

        // CU(params 35..37): control q3 (bit0) -> target q5 (bit2)
        {
            U2 u = u3(p[35], p[36], p[37]);
#pragma unroll
            for (int a = 0; a < 8; a++) {
                if ((a & 1) && !(a & 4)) {
                    c2 t0c = w[a], t1c = w[a | 4];
                    w[a]     = cadd(cmul(u.m00, t0c), cmul(u.m01, t1c));
                    w[a | 4] = cadd(cmul(u.m10, t0c), cmul(u.m11, t1c));
                }
            }
        }

#pragma unroll
        for (int a = 0; a < 8; a++) { Wr[a][tid] = w[a].x; Wi[a][tid] = w[a].y; }
    }
    __syncthreads();
    if (tid < 64) {
        int a = tid >> 3, b = tid & 7;
        float acc = 0.f;
#pragma unroll
        for (int c = 0; c < 8; c++) {
            float z = (c & 4) ? -1.f : 1.f;
            acc += z * (Wr[c][a] * Wr[c][b] + Wi[c][a] * Wi[c][b]);
        }
        C[tid] = (a == b) ? acc : 2.f * acc;   // off-diagonals counted twice
    }
    __syncthreads();   // C visible to all warps; last block-wide barrier

    int r_loc = lane >> 1;          // row within tile
    int h     = lane & 1;           // half: k in {4h..4h+3} of each block

    // ---- per-warp independent pipelined loop ----
    int buf = 0;
    for (int tt = gwarp; tt < ntiles; tt += nwarps) {
        int nxt = tt + nwarps;
        l2_prefetch(tt + PF_DIST * nwarps);   // keep L2 PF_DIST tiles ahead
        if (nxt < ntiles) prefetch(nxt, buf ^ 1);
        __pipeline_commit();          // uniform group counting
        __pipeline_wait_prior(1);     // current tile complete (this thread)
        __syncwarp();                 // cross-lane visibility within warp

        int row = tt * WROWS + r_loc;
        if (row < n) {
            // half-row: float4 a-th chunk = x[8a + 4h .. 8a + 4h + 3]
            float x[32];
            const float* rp = wtile + buf * WTILE + r_loc * ROW_PAD + 4 * h;
#pragma unroll
            for (int a = 0; a < 8; a++) {
                float4 v = *reinterpret_cast<const float4*>(rp + 8 * a);
                x[4*a + 0] = v.x; x[4*a + 1] = v.y; x[4*a + 2] = v.z; x[4*a + 3] = v.w;
            }

            float Q = 0.f, N = 0.f;
#pragma unroll
            for (int a = 0; a < 8; a++) {
#pragma unroll
                for (int b = a; b < 8; b++) {
                    float s = 0.f;
#pragma unroll
                    for (int k = 0; k < 4; k++) s += x[4*a + k] * x[4*b + k];
                    Q += C[8*a + b] * s;
                    if (a == b) N += s;
                }
            }
            // combine the two half-rows
            Q += __shfl_xor_sync(0xFFFFFFFF, Q, 1);
            N += __shfl_xor_sync(0xFFFFFFFF, N, 1);
            if (h == 0) {
                // jnp.isclose(norm,0), atol=1e-8 -> N <= 1e-16 -> psi = e0
                out[row] = (N <= 1e-16f) ? C[0] : __fdividef(Q, N);
            }
        }
        __syncwarp();                 // all lanes done reading buf before refill
        buf ^= 1;
    }
}

extern "C" void kernel_launch(void* const* d_in, const int* in_sizes, int n_in,
                              void* d_out, int out_size) {
    // metadata order: features (B*64 floats), params (54 floats); be defensive.
    int fi = 0, pi = 1;
    if (n_in >= 2 && in_sizes[0] == 54) { fi = 1; pi = 0; }

    const float* feat   = (const float*)d_in[fi];
    const float* params = (const float*)d_in[pi];
    float* out = (float*)d_out;

    int n = in_sizes[fi] / 64;
    int ntiles = (n + WROWS - 1) / WROWS;
    int full_tiles = n / WROWS;           // tiles with no tail handling

    cudaFuncSetAttribute(quadform_kernel,
                         cudaFuncAttributeMaxDynamicSharedMemorySize, SMEM_BYTES);

    // 3 blocks/SM (73.7 KB dynamic smem each) x 148 SMs = 24 warps/SM
    int grid = 148 * 3;
    int maxgrid = (ntiles + WARPS - 1) / WARPS;
    if (grid > maxgrid) grid = maxgrid;

    quadform_kernel<<<grid, TPB, SMEM_BYTES>>>(feat, params, out, n, ntiles,
                                               full_tiles);
}